// round 4
// baseline (speedup 1.0000x reference)
#include <cuda_runtime.h>
#include <stdint.h>

#define K_DIM 4096
#define N_DIM 4096
#define M_DIM 8192   // 4 * 2048
#define BM 128
#define BN 128
#define BK 16
#define NTHREADS 256

typedef unsigned long long u64;

// 64MB scratch for the fused effective weight: Weff[k][n] = W[n][k] + 2*(A@B)[k][n]
__device__ float g_weff[(size_t)K_DIM * N_DIM];

__device__ __forceinline__ u64 pack2(float x, float y) {
    u64 r;
    asm("mov.b64 %0, {%1, %2};"
        : "=l"(r) : "r"(__float_as_uint(x)), "r"(__float_as_uint(y)));
    return r;
}
__device__ __forceinline__ u64 packdup(float x) {
    u64 r;
    unsigned int b = __float_as_uint(x);
    asm("mov.b64 %0, {%1, %1};" : "=l"(r) : "r"(b));
    return r;
}
__device__ __forceinline__ void unpack2(u64 v, float& lo, float& hi) {
    unsigned int l, h;
    asm("mov.b64 {%0, %1}, %2;" : "=r"(l), "=r"(h) : "l"(v));
    lo = __uint_as_float(l);
    hi = __uint_as_float(h);
}
__device__ __forceinline__ void fma2(u64& d, u64 a, u64 b) {
    asm("fma.rn.f32x2 %0, %1, %2, %0;" : "+l"(d) : "l"(a), "l"(b));
}

// ---------------------------------------------------------------------------
// Precompute: Weff[k][n] = W[n][k] + 2 * sum_r A[k][r]*B[r][n]
// 32x32 tiles, transpose through smem so both the W read and Weff write
// are fully coalesced.
// ---------------------------------------------------------------------------
__global__ void build_weff_kernel(const float* __restrict__ w,
                                  const float* __restrict__ la,
                                  const float* __restrict__ lb) {
    __shared__ float wt[32][33];   // wt[n_local][k_local]
    __shared__ float as_[32][17];  // A[k_local][r]
    __shared__ float bs_[16][32];  // B[r][n_local]

    int n0 = blockIdx.x * 32;
    int k0 = blockIdx.y * 32;
    int tx = threadIdx.x;   // 0..31
    int ty = threadIdx.y;   // 0..7
    int tid = ty * 32 + tx;

#pragma unroll
    for (int i = 0; i < 32; i += 8)
        wt[ty + i][tx] = w[(size_t)(n0 + ty + i) * K_DIM + (k0 + tx)];

    for (int i = tid; i < 32 * 16; i += 256) {
        int kk = i >> 4, r = i & 15;
        as_[kk][r] = la[(size_t)(k0 + kk) * 16 + r];
    }
    for (int i = tid; i < 16 * 32; i += 256) {
        int r = i >> 5, nn = i & 31;
        bs_[r][nn] = lb[(size_t)r * N_DIM + (n0 + nn)];
    }
    __syncthreads();

#pragma unroll
    for (int i = 0; i < 32; i += 8) {
        int k = ty + i;
        float s = 0.f;
#pragma unroll
        for (int r = 0; r < 16; r++) s += as_[k][r] * bs_[r][tx];
        g_weff[(size_t)(k0 + k) * N_DIM + (n0 + tx)] = wt[tx][k] + 2.0f * s;
    }
}

// ---------------------------------------------------------------------------
// Main GEMM: C[m][n] = sum_k X[m][k] * Weff[k][n] + bias[n]
// 128x128 block tile, BK=16, 256 threads, 8x8 per-thread microtile.
// Inner product uses packed fma.rn.f32x2 (FFMA2): accumulator pairs along M,
// loaded pair-aligned directly from SMEM (no pack cost for A).
// ---------------------------------------------------------------------------
__global__ __launch_bounds__(NTHREADS, 2)
void sgemm_kernel(const float* __restrict__ X,
                  const float* __restrict__ bias,
                  float* __restrict__ C) {
    __shared__ float As[BK][BM + 4];   // [k][m], padded (transposed stores)
    __shared__ float Bs[BK][BN];       // [k][n]

    const int bm = blockIdx.y * BM;
    const int bn = blockIdx.x * BN;
    const int tid = threadIdx.x;
    const int tm = tid >> 4;    // 0..15 -> m microtile
    const int tn = tid & 15;    // 0..15 -> n microtile

    // global load indices
    const int a_row = tid >> 2;            // 0..63 (and +64)
    const int a_col = (tid & 3) * 4;       // 0,4,8,12
    const int b_row = tid >> 5;            // 0..7 (and +8)
    const int b_col = (tid & 31) * 4;      // 0..124

    u64 acc[4][8];
#pragma unroll
    for (int i = 0; i < 4; i++)
#pragma unroll
        for (int j = 0; j < 8; j++) acc[i][j] = 0ull;

    const float* Xp = X + (size_t)bm * K_DIM;
    const float* Wf = g_weff;

    // prefetch tile 0 into registers
    float4 pa0 = *(const float4*)&Xp[(size_t)a_row * K_DIM + a_col];
    float4 pa1 = *(const float4*)&Xp[(size_t)(a_row + 64) * K_DIM + a_col];
    float4 pb0 = *(const float4*)&Wf[(size_t)b_row * N_DIM + bn + b_col];
    float4 pb1 = *(const float4*)&Wf[(size_t)(b_row + 8) * N_DIM + bn + b_col];

    for (int kt = 0; kt < K_DIM; kt += BK) {
        // stage registers -> smem
        As[a_col + 0][a_row] = pa0.x;
        As[a_col + 1][a_row] = pa0.y;
        As[a_col + 2][a_row] = pa0.z;
        As[a_col + 3][a_row] = pa0.w;
        As[a_col + 0][a_row + 64] = pa1.x;
        As[a_col + 1][a_row + 64] = pa1.y;
        As[a_col + 2][a_row + 64] = pa1.z;
        As[a_col + 3][a_row + 64] = pa1.w;
        *(float4*)&Bs[b_row][b_col] = pb0;
        *(float4*)&Bs[b_row + 8][b_col] = pb1;
        __syncthreads();

        // prefetch next tile (global latency hidden under compute below)
        if (kt + BK < K_DIM) {
            int kn = kt + BK;
            pa0 = *(const float4*)&Xp[(size_t)a_row * K_DIM + kn + a_col];
            pa1 = *(const float4*)&Xp[(size_t)(a_row + 64) * K_DIM + kn + a_col];
            pb0 = *(const float4*)&Wf[(size_t)(kn + b_row) * N_DIM + bn + b_col];
            pb1 = *(const float4*)&Wf[(size_t)(kn + b_row + 8) * N_DIM + bn + b_col];
        }

#pragma unroll
        for (int k = 0; k < BK; k++) {
            // A: 8 m-values as 4 packed f32x2 pairs (pair-aligned LDS.128)
            ulonglong2 av0 = *(const ulonglong2*)&As[k][tm * 8];
            ulonglong2 av1 = *(const ulonglong2*)&As[k][tm * 8 + 4];
            u64 a2[4] = {av0.x, av0.y, av1.x, av1.y};

            float4 bq0 = *(const float4*)&Bs[k][tn * 8];
            float4 bq1 = *(const float4*)&Bs[k][tn * 8 + 4];
            u64 b2[8];
            b2[0] = packdup(bq0.x); b2[1] = packdup(bq0.y);
            b2[2] = packdup(bq0.z); b2[3] = packdup(bq0.w);
            b2[4] = packdup(bq1.x); b2[5] = packdup(bq1.y);
            b2[6] = packdup(bq1.z); b2[7] = packdup(bq1.w);

#pragma unroll
            for (int i2 = 0; i2 < 4; i2++)
#pragma unroll
                for (int j = 0; j < 8; j++)
                    fma2(acc[i2][j], a2[i2], b2[j]);
        }
        __syncthreads();
    }

    // epilogue: unpack, add bias, n-contiguous float4 stores
    float4 bias0 = *(const float4*)&bias[bn + tn * 8];
    float4 bias1 = *(const float4*)&bias[bn + tn * 8 + 4];

#pragma unroll
    for (int i2 = 0; i2 < 4; i2++) {
        float vlo[8], vhi[8];
#pragma unroll
        for (int j = 0; j < 8; j++) unpack2(acc[i2][j], vlo[j], vhi[j]);

        int m0 = bm + tm * 8 + i2 * 2;
        float* c0 = &C[(size_t)m0 * N_DIM + bn + tn * 8];
        float* c1 = &C[(size_t)(m0 + 1) * N_DIM + bn + tn * 8];

        float4 o;
        o.x = vlo[0] + bias0.x; o.y = vlo[1] + bias0.y;
        o.z = vlo[2] + bias0.z; o.w = vlo[3] + bias0.w;
        *(float4*)c0 = o;
        o.x = vlo[4] + bias1.x; o.y = vlo[5] + bias1.y;
        o.z = vlo[6] + bias1.z; o.w = vlo[7] + bias1.w;
        *(float4*)(c0 + 4) = o;

        o.x = vhi[0] + bias0.x; o.y = vhi[1] + bias0.y;
        o.z = vhi[2] + bias0.z; o.w = vhi[3] + bias0.w;
        *(float4*)c1 = o;
        o.x = vhi[4] + bias1.x; o.y = vhi[5] + bias1.y;
        o.z = vhi[6] + bias1.z; o.w = vhi[7] + bias1.w;
        *(float4*)(c1 + 4) = o;
    }
}

extern "C" void kernel_launch(void* const* d_in, const int* in_sizes, int n_in,
                              void* d_out, int out_size) {
    const float* x  = (const float*)d_in[0];   // [4,2048,4096]
    const float* w  = (const float*)d_in[1];   // [4096,4096] (out,in)
    const float* b  = (const float*)d_in[2];   // [4096]
    const float* la = (const float*)d_in[3];   // [4096,16]
    const float* lb = (const float*)d_in[4];   // [16,4096]
    float* out = (float*)d_out;                // [4,2048,4096]

    dim3 g1(N_DIM / 32, K_DIM / 32);
    dim3 t1(32, 8);
    build_weff_kernel<<<g1, t1>>>(w, la, lb);

    dim3 g2(N_DIM / BN, M_DIM / BM);
    sgemm_kernel<<<g2, NTHREADS>>>(x, b, out);
}

// round 6
// speedup vs baseline: 2.1719x; 2.1719x over previous
#include <cuda_runtime.h>
#include <cuda_bf16.h>
#include <stdint.h>

#define K_DIM 4096
#define N_DIM 4096
#define M_DIM 8192

#define BM 128
#define BN 256
#define BK 64                 // bf16 per k-step = 128B row
#define NSEG_KT 64            // k-steps per segment
#define NKT 192               // 3 segments * 64
#define NTHREADS 512
#define STAGES 3
#define A_BYTES (BM * 128)    // 16384
#define B_BYTES (BN * 128)    // 32768
#define STAGE_BYTES (A_BYTES + B_BYTES)   // 49152
#define SMEM_DYN (STAGES * STAGE_BYTES + 256)

typedef unsigned long long u64;

// ---- device scratch (allocation-guard-safe) --------------------------------
__device__ __nv_bfloat16 g_xh[(size_t)M_DIM * K_DIM];
__device__ __nv_bfloat16 g_xl[(size_t)M_DIM * K_DIM];
__device__ __nv_bfloat16 g_wh[(size_t)N_DIM * K_DIM];  // [n][k] : Weff^T hi
__device__ __nv_bfloat16 g_wl[(size_t)N_DIM * K_DIM];

__device__ __forceinline__ uint32_t smem_to_u32(const void* p) {
    uint32_t a;
    asm("{ .reg .u64 t; cvta.to.shared.u64 t, %1; cvt.u32.u64 %0, t; }"
        : "=r"(a) : "l"(p));
    return a;
}
__device__ __forceinline__ void cp16(uint32_t dst, const void* src) {
    asm volatile("cp.async.cg.shared.global [%0], [%1], 16;\n" :: "r"(dst), "l"(src));
}
#define CP_COMMIT() asm volatile("cp.async.commit_group;\n" ::: "memory")
#define CP_WAIT(n) asm volatile("cp.async.wait_group %0;\n" :: "n"(n) : "memory")

__device__ __forceinline__ void ldsm_x4(uint32_t (&r)[4], uint32_t addr) {
    asm volatile("ldmatrix.sync.aligned.m8n8.x4.shared.b16 {%0,%1,%2,%3}, [%4];"
                 : "=r"(r[0]), "=r"(r[1]), "=r"(r[2]), "=r"(r[3]) : "r"(addr));
}
__device__ __forceinline__ void mma_bf16(float (&c)[4], const uint32_t (&a)[4],
                                         uint32_t b0, uint32_t b1) {
    asm volatile(
        "mma.sync.aligned.m16n8k16.row.col.f32.bf16.bf16.f32 "
        "{%0,%1,%2,%3}, {%4,%5,%6,%7}, {%8,%9}, {%0,%1,%2,%3};"
        : "+f"(c[0]), "+f"(c[1]), "+f"(c[2]), "+f"(c[3])
        : "r"(a[0]), "r"(a[1]), "r"(a[2]), "r"(a[3]), "r"(b0), "r"(b1));
}

// ---------------------------------------------------------------------------
// convert X -> bf16 hi/lo
// ---------------------------------------------------------------------------
__global__ void convert_x_kernel(const float* __restrict__ x) {
    size_t i = ((size_t)blockIdx.x * 256 + threadIdx.x) * 8;
    float4 a = *(const float4*)(x + i);
    float4 b = *(const float4*)(x + i + 4);
    float v[8] = {a.x, a.y, a.z, a.w, b.x, b.y, b.z, b.w};
    union { __nv_bfloat16 h[8]; uint4 u; } H, L;
#pragma unroll
    for (int j = 0; j < 8; j++) {
        H.h[j] = __float2bfloat16(v[j]);
        L.h[j] = __float2bfloat16(v[j] - __bfloat162float(H.h[j]));
    }
    *(uint4*)(g_xh + i) = H.u;
    *(uint4*)(g_xl + i) = L.u;
}

// ---------------------------------------------------------------------------
// build Wt[n][k] = W[n][k] + 2 * sum_r A[k][r]*B[r][n], split bf16 hi/lo
// ---------------------------------------------------------------------------
__global__ void build_w_kernel(const float* __restrict__ w,
                               const float* __restrict__ la,
                               const float* __restrict__ lb) {
    __shared__ float as_[32][17];
    __shared__ float bs_[16][33];
    int k0 = blockIdx.x * 32, n0 = blockIdx.y * 32;
    int tx = threadIdx.x;  // k_local
    int ty = threadIdx.y;  // 0..7
    int tid = ty * 32 + tx;
    for (int i = tid; i < 512; i += 256) {
        int kk = i >> 4, r = i & 15;
        as_[kk][r] = la[(size_t)(k0 + kk) * 16 + r];
    }
    for (int i = tid; i < 512; i += 256) {
        int r = i >> 5, nn = i & 31;
        bs_[r][nn] = lb[(size_t)r * N_DIM + (n0 + nn)];
    }
    __syncthreads();
#pragma unroll
    for (int i = 0; i < 4; i++) {
        int nl = ty + i * 8;
        float s = 0.f;
#pragma unroll
        for (int r = 0; r < 16; r++) s += as_[tx][r] * bs_[r][nl];
        size_t idx = (size_t)(n0 + nl) * K_DIM + k0 + tx;
        float val = w[idx] + 2.0f * s;
        __nv_bfloat16 h = __float2bfloat16(val);
        g_wh[idx] = h;
        g_wl[idx] = __float2bfloat16(val - __bfloat162float(h));
    }
}

// ---------------------------------------------------------------------------
// HMMA GEMM: C[128x256 tile] = Xh@Wh^T + Xh@Wl^T + Xl@Wh^T + bias
// 16 warps (2 M x 8 N), warp tile 64x32, mma.sync m16n8k16 bf16.
// ---------------------------------------------------------------------------
__global__ void __launch_bounds__(NTHREADS, 1)
gemm_hmma_kernel(const float* __restrict__ bias, float* __restrict__ C) {
    extern __shared__ char smraw[];
    const uint32_t sb = (smem_to_u32(smraw) + 127u) & ~127u;

    const int tid = threadIdx.x;
    const int wid = tid >> 5;
    const int lid = tid & 31;
    const int wm = wid & 1;        // 0..1  -> 64-row slab
    const int wn = wid >> 1;       // 0..7  -> 32-col slab
    const int bm = blockIdx.y * BM;
    const int bn = blockIdx.x * BN;

    float acc[4][4][4];
#pragma unroll
    for (int i = 0; i < 4; i++)
#pragma unroll
        for (int j = 0; j < 4; j++)
#pragma unroll
            for (int q = 0; q < 4; q++) acc[i][j][q] = 0.f;

    // ---- loader geometry ----
    const int arow = tid >> 2;            // 0..127
    const int ac0 = (tid & 3) * 2;        // chunks {ac0, ac0+1}
    const int brow = tid >> 1;            // 0..255
    const int bc0 = (tid & 1) * 4;        // chunks {bc0..bc0+3}
    const size_t Kb = (size_t)K_DIM * 2;  // row stride in bytes

    const char* xh_p = (const char*)g_xh + (size_t)(bm + arow) * Kb + (size_t)ac0 * 16;
    const char* xl_p = (const char*)g_xl + (size_t)(bm + arow) * Kb + (size_t)ac0 * 16;
    const char* wh_p = (const char*)g_wh + (size_t)(bn + brow) * Kb + (size_t)bc0 * 16;
    const char* wl_p = (const char*)g_wl + (size_t)(bn + brow) * Kb + (size_t)bc0 * 16;

    const uint32_t a_dst0 = sb + (uint32_t)arow * 128u + (uint32_t)((ac0 ^ (arow & 7)) * 16);
    const uint32_t a_dst1 = sb + (uint32_t)arow * 128u + (uint32_t)(((ac0 + 1) ^ (arow & 7)) * 16);
    uint32_t b_dst[4];
#pragma unroll
    for (int j = 0; j < 4; j++)
        b_dst[j] = sb + A_BYTES + (uint32_t)brow * 128u +
                   (uint32_t)(((bc0 + j) ^ (brow & 7)) * 16);

    auto load_stage = [&](int s, int kt) {
        const int seg = kt >> 6;
        const size_t koff = (size_t)(kt & (NSEG_KT - 1)) * 128;  // 64 bf16 = 128B
        const char* A = (seg == 2 ? xl_p : xh_p) + koff;
        const char* B = (seg == 1 ? wl_p : wh_p) + koff;
        const uint32_t st = (uint32_t)s * STAGE_BYTES;
        cp16(a_dst0 + st, A);
        cp16(a_dst1 + st, A + 16);
#pragma unroll
        for (int j = 0; j < 4; j++) cp16(b_dst[j] + st, B + j * 16);
        CP_COMMIT();
    };

    // ---- ldmatrix per-lane geometry (stage-relative) ----
    uint32_t a_rel[4], a_sw[4];
    const int a_half = lid >> 4;           // chunk half for A x4
#pragma unroll
    for (int mi = 0; mi < 4; mi++) {
        int row = wm * 64 + mi * 16 + (lid & 15);
        a_rel[mi] = (uint32_t)row * 128u;
        a_sw[mi] = (uint32_t)(row & 7);
    }
    uint32_t b_rel[2], b_sw[2];
    const int b_kh = (lid >> 3) & 1;       // k-half for B x4
    const int b_nbl = lid >> 4;            // which of the 2 n8 blocks in this x4
#pragma unroll
    for (int bj = 0; bj < 2; bj++) {
        int row = wn * 32 + (bj * 2 + b_nbl) * 8 + (lid & 7);
        b_rel[bj] = A_BYTES + (uint32_t)row * 128u;
        b_sw[bj] = (uint32_t)(row & 7);
    }

    // ---- prologue ----
    load_stage(0, 0);
    load_stage(1, 1);

    for (int kt = 0; kt < NKT; kt++) {
        const int s = kt % STAGES;
        if (kt == NKT - 1) CP_WAIT(0); else CP_WAIT(1);
        __syncthreads();

        if (kt + 2 < NKT) load_stage((kt + 2) % STAGES, kt + 2);

        const uint32_t stb = sb + (uint32_t)s * STAGE_BYTES;
#pragma unroll
        for (int k16 = 0; k16 < 4; k16++) {
            uint32_t afr[4][4];
#pragma unroll
            for (int mi = 0; mi < 4; mi++) {
                uint32_t c = (uint32_t)(k16 * 2 + a_half) ^ a_sw[mi];
                ldsm_x4(afr[mi], stb + a_rel[mi] + c * 16u);
            }
            uint32_t bfr[4][2];
#pragma unroll
            for (int bj = 0; bj < 2; bj++) {
                uint32_t c = (uint32_t)(k16 * 2 + b_kh) ^ b_sw[bj];
                uint32_t r[4];
                ldsm_x4(r, stb + b_rel[bj] + c * 16u);
                bfr[bj * 2 + 0][0] = r[0]; bfr[bj * 2 + 0][1] = r[1];
                bfr[bj * 2 + 1][0] = r[2]; bfr[bj * 2 + 1][1] = r[3];
            }
#pragma unroll
            for (int mi = 0; mi < 4; mi++)
#pragma unroll
                for (int ni = 0; ni < 4; ni++)
                    mma_bf16(acc[mi][ni], afr[mi], bfr[ni][0], bfr[ni][1]);
        }
    }

    // ---- epilogue: bias + store ----
#pragma unroll
    for (int ni = 0; ni < 4; ni++) {
        const int gc = bn + wn * 32 + ni * 8 + (lid & 3) * 2;
        const float2 bv = *(const float2*)&bias[gc];
#pragma unroll
        for (int mi = 0; mi < 4; mi++) {
            const int gr = bm + wm * 64 + mi * 16 + (lid >> 2);
            float2 o0, o1;
            o0.x = acc[mi][ni][0] + bv.x;
            o0.y = acc[mi][ni][1] + bv.y;
            o1.x = acc[mi][ni][2] + bv.x;
            o1.y = acc[mi][ni][3] + bv.y;
            *(float2*)&C[(size_t)gr * N_DIM + gc] = o0;
            *(float2*)&C[(size_t)(gr + 8) * N_DIM + gc] = o1;
        }
    }
}

// ---------------------------------------------------------------------------
extern "C" void kernel_launch(void* const* d_in, const int* in_sizes, int n_in,
                              void* d_out, int out_size) {
    const float* x  = (const float*)d_in[0];   // [4,2048,4096]
    const float* w  = (const float*)d_in[1];   // [4096,4096] (out,in)
    const float* b  = (const float*)d_in[2];   // [4096]
    const float* la = (const float*)d_in[3];   // [4096,16]
    const float* lb = (const float*)d_in[4];   // [16,4096]
    float* out = (float*)d_out;

    convert_x_kernel<<<(M_DIM * K_DIM) / (256 * 8), 256>>>(x);
    build_w_kernel<<<dim3(K_DIM / 32, N_DIM / 32), dim3(32, 8)>>>(w, la, lb);

    cudaFuncSetAttribute(gemm_hmma_kernel,
                         cudaFuncAttributeMaxDynamicSharedMemorySize, SMEM_DYN);
    gemm_hmma_kernel<<<dim3(N_DIM / BN, M_DIM / BM), NTHREADS, SMEM_DYN>>>(b, out);
}

// round 8
// speedup vs baseline: 2.7095x; 1.2475x over previous
#include <cuda_runtime.h>
#include <cuda_fp16.h>
#include <stdint.h>

#define K_DIM 4096
#define N_DIM 4096
#define M_DIM 8192

#define BM 128
#define BN 256
#define BK 64                 // fp16 per k-step = 128B row
#define NSEG_KT 64            // k-steps per segment
#define NKT 192               // 3 segments
#define NTHREADS 256
#define STAGES 4
#define A_BYTES (BM * 128)    // 16384
#define B_BYTES (BN * 128)    // 32768
#define STAGE_BYTES (A_BYTES + B_BYTES)   // 49152
#define SMEM_DYN (STAGES * STAGE_BYTES + 256)

typedef unsigned long long u64;

// ---- device scratch (allocation-guard-safe) --------------------------------
__device__ __half g_xh[(size_t)M_DIM * K_DIM];
__device__ __half g_xl[(size_t)M_DIM * K_DIM];
__device__ __half g_wh[(size_t)N_DIM * K_DIM];  // [n][k] : Weff^T hi
__device__ __half g_wl[(size_t)N_DIM * K_DIM];

__device__ __forceinline__ uint32_t smem_to_u32(const void* p) {
    uint32_t a;
    asm("{ .reg .u64 t; cvta.to.shared.u64 t, %1; cvt.u32.u64 %0, t; }"
        : "=r"(a) : "l"(p));
    return a;
}
__device__ __forceinline__ void cp16(uint32_t dst, const void* src) {
    asm volatile("cp.async.cg.shared.global [%0], [%1], 16;\n" :: "r"(dst), "l"(src));
}
#define CP_COMMIT() asm volatile("cp.async.commit_group;\n" ::: "memory")
#define CP_WAIT(n) asm volatile("cp.async.wait_group %0;\n" :: "n"(n) : "memory")

__device__ __forceinline__ void ldsm_x4(uint32_t (&r)[4], uint32_t addr) {
    asm volatile("ldmatrix.sync.aligned.m8n8.x4.shared.b16 {%0,%1,%2,%3}, [%4];"
                 : "=r"(r[0]), "=r"(r[1]), "=r"(r[2]), "=r"(r[3]) : "r"(addr));
}
// fp32-accum HMMA (main term)
__device__ __forceinline__ void mma_f32acc(float (&c)[4], const uint32_t (&a)[4],
                                           uint32_t b0, uint32_t b1) {
    asm volatile(
        "mma.sync.aligned.m16n8k16.row.col.f32.f16.f16.f32 "
        "{%0,%1,%2,%3}, {%4,%5,%6,%7}, {%8,%9}, {%0,%1,%2,%3};"
        : "+f"(c[0]), "+f"(c[1]), "+f"(c[2]), "+f"(c[3])
        : "r"(a[0]), "r"(a[1]), "r"(a[2]), "r"(a[3]), "r"(b0), "r"(b1));
}
// fp16-accum HMMA (correction terms; values ~1e-3, precision ample)
__device__ __forceinline__ void mma_f16acc(uint32_t (&c)[2], const uint32_t (&a)[4],
                                           uint32_t b0, uint32_t b1) {
    asm volatile(
        "mma.sync.aligned.m16n8k16.row.col.f16.f16.f16.f16 "
        "{%0,%1}, {%2,%3,%4,%5}, {%6,%7}, {%0,%1};"
        : "+r"(c[0]), "+r"(c[1])
        : "r"(a[0]), "r"(a[1]), "r"(a[2]), "r"(a[3]), "r"(b0), "r"(b1));
}

// ---------------------------------------------------------------------------
// convert X -> fp16 hi/lo
// ---------------------------------------------------------------------------
__global__ void convert_x_kernel(const float* __restrict__ x) {
    size_t i = ((size_t)blockIdx.x * 256 + threadIdx.x) * 8;
    float4 a = *(const float4*)(x + i);
    float4 b = *(const float4*)(x + i + 4);
    float v[8] = {a.x, a.y, a.z, a.w, b.x, b.y, b.z, b.w};
    union { __half h[8]; uint4 u; } H, L;
#pragma unroll
    for (int j = 0; j < 8; j++) {
        H.h[j] = __float2half(v[j]);
        L.h[j] = __float2half(v[j] - __half2float(H.h[j]));
    }
    *(uint4*)(g_xh + i) = H.u;
    *(uint4*)(g_xl + i) = L.u;
}

// ---------------------------------------------------------------------------
// build Wt[n][k] = W[n][k] + 2 * sum_r A[k][r]*B[r][n], split fp16 hi/lo
// ---------------------------------------------------------------------------
__global__ void build_w_kernel(const float* __restrict__ w,
                               const float* __restrict__ la,
                               const float* __restrict__ lb) {
    __shared__ float as_[32][17];
    __shared__ float bs_[16][33];
    int k0 = blockIdx.x * 32, n0 = blockIdx.y * 32;
    int tx = threadIdx.x;  // k_local
    int ty = threadIdx.y;  // 0..7
    int tid = ty * 32 + tx;
    for (int i = tid; i < 512; i += 256) {
        int kk = i >> 4, r = i & 15;
        as_[kk][r] = la[(size_t)(k0 + kk) * 16 + r];
    }
    for (int i = tid; i < 512; i += 256) {
        int r = i >> 5, nn = i & 31;
        bs_[r][nn] = lb[(size_t)r * N_DIM + (n0 + nn)];
    }
    __syncthreads();
#pragma unroll
    for (int i = 0; i < 4; i++) {
        int nl = ty + i * 8;
        float s = 0.f;
#pragma unroll
        for (int r = 0; r < 16; r++) s += as_[tx][r] * bs_[r][nl];
        size_t idx = (size_t)(n0 + nl) * K_DIM + k0 + tx;
        float val = w[idx] + 2.0f * s;
        __half h = __float2half(val);
        g_wh[idx] = h;
        g_wl[idx] = __float2half(val - __half2float(h));
    }
}

// ---------------------------------------------------------------------------
// HMMA GEMM: C = Xh@Wh^T (f32 acc) + [Xh@Wl^T + Xl@Wh^T] (f16 acc) + bias
// 8 warps (2m x 4n), warp tile 64x64, 4-stage cp.async pipeline.
// Segment order: corrections first (kt 0..127, f16 acc), main last (f32 acc).
// ---------------------------------------------------------------------------
__global__ void __launch_bounds__(NTHREADS, 1)
gemm_hmma_kernel(const float* __restrict__ bias, float* __restrict__ C) {
    extern __shared__ char smraw[];
    const uint32_t sb = (smem_to_u32(smraw) + 127u) & ~127u;

    const int tid = threadIdx.x;
    const int wid = tid >> 5;
    const int lid = tid & 31;
    const int wm = wid & 1;        // 0..1 -> 64-row slab
    const int wn = wid >> 1;       // 0..3 -> 64-col slab
    const int bm = blockIdx.y * BM;
    const int bn = blockIdx.x * BN;

    uint32_t acc_h[4][8][2];       // f16x2 accum for correction terms
#pragma unroll
    for (int i = 0; i < 4; i++)
#pragma unroll
        for (int j = 0; j < 8; j++) { acc_h[i][j][0] = 0u; acc_h[i][j][1] = 0u; }
    float acc_f[4][8][4];          // f32 accum (initialized at segment switch)

    // ---- loader geometry: thread t handles chunks c = t + 256*i ----
    const int arow = tid >> 3;             // 0..31
    const int ach = tid & 7;               // chunk in 128B row
    const size_t Kb = (size_t)K_DIM * 2;   // row stride bytes
    const uint32_t dsw = (uint32_t)((ach ^ (arow & 7)) * 16);
    const uint32_t a_dst = sb + (uint32_t)arow * 128u + dsw;            // +4096*i
    const uint32_t b_dst = sb + A_BYTES + (uint32_t)arow * 128u + dsw;  // +4096*i

    const char* xh_p = (const char*)g_xh + (size_t)(bm + arow) * Kb + (size_t)ach * 16;
    const char* xl_p = (const char*)g_xl + (size_t)(bm + arow) * Kb + (size_t)ach * 16;
    const char* wh_p = (const char*)g_wh + (size_t)(bn + arow) * Kb + (size_t)ach * 16;
    const char* wl_p = (const char*)g_wl + (size_t)(bn + arow) * Kb + (size_t)ach * 16;
    const size_t gstride = 32 * Kb;        // +32 rows

    // segment order: 0: Xh*Wl, 1: Xl*Wh, 2: Xh*Wh
    auto load_stage = [&](int s, int kt) {
        const int seg = kt >> 6;
        const size_t koff = (size_t)(kt & (NSEG_KT - 1)) * 128;
        const char* A = (seg == 1 ? xl_p : xh_p) + koff;
        const char* B = (seg == 0 ? wl_p : wh_p) + koff;
        const uint32_t st = (uint32_t)s * STAGE_BYTES;
#pragma unroll
        for (int i = 0; i < 4; i++)        // A: 128 rows
            cp16(a_dst + st + (uint32_t)i * 4096u, A + i * gstride);
#pragma unroll
        for (int i = 0; i < 8; i++)        // B: 256 rows
            cp16(b_dst + st + (uint32_t)i * 4096u, B + i * gstride);
        CP_COMMIT();
    };

    // ---- ldmatrix per-lane geometry (stage-relative) ----
    uint32_t a_rel[4], a_sw[4];
    const int a_half = lid >> 4;
#pragma unroll
    for (int mi = 0; mi < 4; mi++) {
        int row = wm * 64 + mi * 16 + (lid & 15);
        a_rel[mi] = (uint32_t)row * 128u;
        a_sw[mi] = (uint32_t)(row & 7);
    }
    uint32_t b_rel[4], b_sw[4];
    const int b_kh = (lid >> 3) & 1;
    const int b_nbl = lid >> 4;
#pragma unroll
    for (int bj = 0; bj < 4; bj++) {
        int row = wn * 64 + (bj * 2 + b_nbl) * 8 + (lid & 7);
        b_rel[bj] = A_BYTES + (uint32_t)row * 128u;
        b_sw[bj] = (uint32_t)(row & 7);
    }

    // ---- prologue: fill 3 of 4 stages ----
    load_stage(0, 0);
    load_stage(1, 1);
    load_stage(2, 2);

    for (int kt = 0; kt < NKT; kt++) {
        const int s = kt & 3;
        if (kt < NKT - 2) CP_WAIT(2);
        else if (kt == NKT - 2) CP_WAIT(1);
        else CP_WAIT(0);
        __syncthreads();

        if (kt + 3 < NKT) load_stage((kt + 3) & 3, kt + 3);

        // segment switch: fold f16 corrections into the f32 accumulators
        if (kt == 2 * NSEG_KT) {
#pragma unroll
            for (int mi = 0; mi < 4; mi++)
#pragma unroll
                for (int ni = 0; ni < 8; ni++) {
                    float2 lo = __half22float2(*(__half2*)&acc_h[mi][ni][0]);
                    float2 hi = __half22float2(*(__half2*)&acc_h[mi][ni][1]);
                    acc_f[mi][ni][0] = lo.x; acc_f[mi][ni][1] = lo.y;
                    acc_f[mi][ni][2] = hi.x; acc_f[mi][ni][3] = hi.y;
                }
        }

        const uint32_t stb = sb + (uint32_t)s * STAGE_BYTES;
        if (kt < 2 * NSEG_KT) {
#pragma unroll
            for (int k16 = 0; k16 < 4; k16++) {
                uint32_t afr[4][4];
#pragma unroll
                for (int mi = 0; mi < 4; mi++) {
                    uint32_t c = (uint32_t)(k16 * 2 + a_half) ^ a_sw[mi];
                    ldsm_x4(afr[mi], stb + a_rel[mi] + c * 16u);
                }
                uint32_t bfr[8][2];
#pragma unroll
                for (int bj = 0; bj < 4; bj++) {
                    uint32_t c = (uint32_t)(k16 * 2 + b_kh) ^ b_sw[bj];
                    uint32_t r[4];
                    ldsm_x4(r, stb + b_rel[bj] + c * 16u);
                    bfr[bj * 2 + 0][0] = r[0]; bfr[bj * 2 + 0][1] = r[1];
                    bfr[bj * 2 + 1][0] = r[2]; bfr[bj * 2 + 1][1] = r[3];
                }
#pragma unroll
                for (int mi = 0; mi < 4; mi++)
#pragma unroll
                    for (int ni = 0; ni < 8; ni++)
                        mma_f16acc(acc_h[mi][ni], afr[mi], bfr[ni][0], bfr[ni][1]);
            }
        } else {
#pragma unroll
            for (int k16 = 0; k16 < 4; k16++) {
                uint32_t afr[4][4];
#pragma unroll
                for (int mi = 0; mi < 4; mi++) {
                    uint32_t c = (uint32_t)(k16 * 2 + a_half) ^ a_sw[mi];
                    ldsm_x4(afr[mi], stb + a_rel[mi] + c * 16u);
                }
                uint32_t bfr[8][2];
#pragma unroll
                for (int bj = 0; bj < 4; bj++) {
                    uint32_t c = (uint32_t)(k16 * 2 + b_kh) ^ b_sw[bj];
                    uint32_t r[4];
                    ldsm_x4(r, stb + b_rel[bj] + c * 16u);
                    bfr[bj * 2 + 0][0] = r[0]; bfr[bj * 2 + 0][1] = r[1];
                    bfr[bj * 2 + 1][0] = r[2]; bfr[bj * 2 + 1][1] = r[3];
                }
#pragma unroll
                for (int mi = 0; mi < 4; mi++)
#pragma unroll
                    for (int ni = 0; ni < 8; ni++)
                        mma_f32acc(acc_f[mi][ni], afr[mi], bfr[ni][0], bfr[ni][1]);
            }
        }
    }

    // ---- epilogue: bias + store ----
#pragma unroll
    for (int ni = 0; ni < 8; ni++) {
        const int gc = bn + wn * 64 + ni * 8 + (lid & 3) * 2;
        const float2 bv = *(const float2*)&bias[gc];
#pragma unroll
        for (int mi = 0; mi < 4; mi++) {
            const int gr = bm + wm * 64 + mi * 16 + (lid >> 2);
            float2 o0, o1;
            o0.x = acc_f[mi][ni][0] + bv.x;
            o0.y = acc_f[mi][ni][1] + bv.y;
            o1.x = acc_f[mi][ni][2] + bv.x;
            o1.y = acc_f[mi][ni][3] + bv.y;
            *(float2*)&C[(size_t)gr * N_DIM + gc] = o0;
            *(float2*)&C[(size_t)(gr + 8) * N_DIM + gc] = o1;
        }
    }
}

// ---------------------------------------------------------------------------
extern "C" void kernel_launch(void* const* d_in, const int* in_sizes, int n_in,
                              void* d_out, int out_size) {
    const float* x  = (const float*)d_in[0];   // [4,2048,4096]
    const float* w  = (const float*)d_in[1];   // [4096,4096] (out,in)
    const float* b  = (const float*)d_in[2];   // [4096]
    const float* la = (const float*)d_in[3];   // [4096,16]
    const float* lb = (const float*)d_in[4];   // [16,4096]
    float* out = (float*)d_out;

    convert_x_kernel<<<(M_DIM * K_DIM) / (256 * 8), 256>>>(x);
    build_w_kernel<<<dim3(K_DIM / 32, N_DIM / 32), dim3(32, 8)>>>(w, la, lb);

    cudaFuncSetAttribute(gemm_hmma_kernel,
                         cudaFuncAttributeMaxDynamicSharedMemorySize, SMEM_DYN);
    gemm_hmma_kernel<<<dim3(N_DIM / BN, M_DIM / BM), NTHREADS, SMEM_DYN>>>(b, out);
}

// round 12
// speedup vs baseline: 3.9472x; 1.4568x over previous
#include <cuda_runtime.h>
#include <cuda_fp16.h>
#include <stdint.h>

#define K_DIM 4096
#define N_DIM 4096
#define M_DIM 8192

#define BM 128
#define BN 256
#define BK 64                 // fp16 per k-step = 128B row
#define NSEG_KT 64            // k-steps per segment
#define NKT 128               // 2 segments: Xh*Wl (f16acc), Xh*Wh (f32acc)
#define NTHREADS 256
#define STAGES 4
#define A_BYTES (BM * 128)    // 16384
#define B_BYTES (BN * 128)    // 32768
#define STAGE_BYTES (A_BYTES + B_BYTES)   // 49152
#define SMEM_DYN (STAGES * STAGE_BYTES + 256)

typedef unsigned long long u64;

// ---- device scratch (allocation-guard-safe) --------------------------------
__device__ __half g_xh[(size_t)M_DIM * K_DIM];
__device__ __half g_wh[(size_t)N_DIM * K_DIM];  // [n][k] : Weff^T hi
__device__ __half g_wl[(size_t)N_DIM * K_DIM];  // [n][k] : Weff^T residual

__device__ __forceinline__ uint32_t smem_to_u32(const void* p) {
    uint32_t a;
    asm("{ .reg .u64 t; cvta.to.shared.u64 t, %1; cvt.u32.u64 %0, t; }"
        : "=r"(a) : "l"(p));
    return a;
}
__device__ __forceinline__ void cp16(uint32_t dst, const void* src) {
    asm volatile("cp.async.cg.shared.global [%0], [%1], 16;\n" :: "r"(dst), "l"(src));
}
#define CP_COMMIT() asm volatile("cp.async.commit_group;\n" ::: "memory")
#define CP_WAIT(n) asm volatile("cp.async.wait_group %0;\n" :: "n"(n) : "memory")

__device__ __forceinline__ void ldsm_x4(uint32_t (&r)[4], uint32_t addr) {
    asm volatile("ldmatrix.sync.aligned.m8n8.x4.shared.b16 {%0,%1,%2,%3}, [%4];"
                 : "=r"(r[0]), "=r"(r[1]), "=r"(r[2]), "=r"(r[3]) : "r"(addr));
}
// fp32-accum HMMA (main term)
__device__ __forceinline__ void mma_f32acc(float (&c)[4], const uint32_t (&a)[4],
                                           uint32_t b0, uint32_t b1) {
    asm volatile(
        "mma.sync.aligned.m16n8k16.row.col.f32.f16.f16.f32 "
        "{%0,%1,%2,%3}, {%4,%5,%6,%7}, {%8,%9}, {%0,%1,%2,%3};"
        : "+f"(c[0]), "+f"(c[1]), "+f"(c[2]), "+f"(c[3])
        : "r"(a[0]), "r"(a[1]), "r"(a[2]), "r"(a[3]), "r"(b0), "r"(b1));
}
// fp16-accum HMMA (correction term; values ~1e-3, precision ample)
__device__ __forceinline__ void mma_f16acc(uint32_t (&c)[2], const uint32_t (&a)[4],
                                           uint32_t b0, uint32_t b1) {
    asm volatile(
        "mma.sync.aligned.m16n8k16.row.col.f16.f16.f16.f16 "
        "{%0,%1}, {%2,%3,%4,%5}, {%6,%7}, {%0,%1};"
        : "+r"(c[0]), "+r"(c[1])
        : "r"(a[0]), "r"(a[1]), "r"(a[2]), "r"(a[3]), "r"(b0), "r"(b1));
}

// ---------------------------------------------------------------------------
// merged prep: grid.y==0 -> convert X to fp16 hi; grid.y==1 -> build W splits
// ---------------------------------------------------------------------------
__global__ void prep_kernel(const float* __restrict__ x,
                            const float* __restrict__ w,
                            const float* __restrict__ la,
                            const float* __restrict__ lb) {
    __shared__ float as_[32][17];
    __shared__ float bs_[16][33];
    const int tid = threadIdx.x;

    if (blockIdx.y == 0) {
        // ---- convert X -> fp16 hi only ----
        size_t i = ((size_t)blockIdx.x * 256 + tid) * 8;
        float4 a = *(const float4*)(x + i);
        float4 b = *(const float4*)(x + i + 4);
        float v[8] = {a.x, a.y, a.z, a.w, b.x, b.y, b.z, b.w};
        union { __half h[8]; uint4 u; } H;
#pragma unroll
        for (int j = 0; j < 8; j++) H.h[j] = __float2half(v[j]);
        *(uint4*)(g_xh + i) = H.u;
        return;
    }

    // ---- build Wt[n][k] = W[n][k] + 2*sum_r A[k][r]*B[r][n], split hi/lo ----
    const int k0 = (blockIdx.x & 127) * 32;
    const int n0 = (blockIdx.x >> 7) * 32;
    const int tx = tid & 31;   // k_local
    const int ty = tid >> 5;   // 0..7
    for (int i = tid; i < 512; i += 256) {
        int kk = i >> 4, r = i & 15;
        as_[kk][r] = la[(size_t)(k0 + kk) * 16 + r];
    }
    for (int i = tid; i < 512; i += 256) {
        int r = i >> 5, nn = i & 31;
        bs_[r][nn] = lb[(size_t)r * N_DIM + (n0 + nn)];
    }
    __syncthreads();
#pragma unroll
    for (int i = 0; i < 4; i++) {
        int nl = ty + i * 8;
        float s = 0.f;
#pragma unroll
        for (int r = 0; r < 16; r++) s += as_[tx][r] * bs_[r][nl];
        size_t idx = (size_t)(n0 + nl) * K_DIM + k0 + tx;
        float val = w[idx] + 2.0f * s;
        __half h = __float2half(val);
        g_wh[idx] = h;
        g_wl[idx] = __float2half(val - __half2float(h));
    }
}

// ---------------------------------------------------------------------------
// HMMA GEMM: C = Xh@Wl^T (f16 acc) + Xh@Wh^T (f32 acc) + bias
// 8 warps (2m x 4n), warp tile 64x64, 4-stage cp.async pipeline.
// ---------------------------------------------------------------------------
__global__ void __launch_bounds__(NTHREADS, 1)
gemm_hmma_kernel(const float* __restrict__ bias, float* __restrict__ C) {
    extern __shared__ char smraw[];
    const uint32_t sb = (smem_to_u32(smraw) + 127u) & ~127u;

    const int tid = threadIdx.x;
    const int wid = tid >> 5;
    const int lid = tid & 31;
    const int wm = wid & 1;        // 0..1 -> 64-row slab
    const int wn = wid >> 1;       // 0..3 -> 64-col slab
    const int bm = blockIdx.y * BM;
    const int bn = blockIdx.x * BN;

    uint32_t acc_h[4][8][2];       // f16x2 accum for correction term
#pragma unroll
    for (int i = 0; i < 4; i++)
#pragma unroll
        for (int j = 0; j < 8; j++) { acc_h[i][j][0] = 0u; acc_h[i][j][1] = 0u; }
    float acc_f[4][8][4];          // f32 accum (initialized at segment switch)

    // ---- loader geometry: thread t handles chunks c = t + 256*i ----
    const int arow = tid >> 3;             // 0..31
    const int ach = tid & 7;               // chunk in 128B row
    const size_t Kb = (size_t)K_DIM * 2;   // row stride bytes
    const uint32_t dsw = (uint32_t)((ach ^ (arow & 7)) * 16);
    const uint32_t a_dst = sb + (uint32_t)arow * 128u + dsw;            // +4096*i
    const uint32_t b_dst = sb + A_BYTES + (uint32_t)arow * 128u + dsw;  // +4096*i

    const char* xh_p = (const char*)g_xh + (size_t)(bm + arow) * Kb + (size_t)ach * 16;
    const char* wh_p = (const char*)g_wh + (size_t)(bn + arow) * Kb + (size_t)ach * 16;
    const char* wl_p = (const char*)g_wl + (size_t)(bn + arow) * Kb + (size_t)ach * 16;
    const size_t gstride = 32 * Kb;        // +32 rows

    // segment order: 0: Xh*Wl (f16 acc), 1: Xh*Wh (f32 acc)
    auto load_stage = [&](int s, int kt) {
        const int seg = kt >> 6;
        const size_t koff = (size_t)(kt & (NSEG_KT - 1)) * 128;
        const char* A = xh_p + koff;
        const char* B = (seg == 0 ? wl_p : wh_p) + koff;
        const uint32_t st = (uint32_t)s * STAGE_BYTES;
#pragma unroll
        for (int i = 0; i < 4; i++)        // A: 128 rows
            cp16(a_dst + st + (uint32_t)i * 4096u, A + i * gstride);
#pragma unroll
        for (int i = 0; i < 8; i++)        // B: 256 rows
            cp16(b_dst + st + (uint32_t)i * 4096u, B + i * gstride);
        CP_COMMIT();
    };

    // ---- ldmatrix per-lane geometry (stage-relative) ----
    uint32_t a_rel[4], a_sw[4];
    const int a_half = lid >> 4;
#pragma unroll
    for (int mi = 0; mi < 4; mi++) {
        int row = wm * 64 + mi * 16 + (lid & 15);
        a_rel[mi] = (uint32_t)row * 128u;
        a_sw[mi] = (uint32_t)(row & 7);
    }
    uint32_t b_rel[4], b_sw[4];
    const int b_kh = (lid >> 3) & 1;
    const int b_nbl = lid >> 4;
#pragma unroll
    for (int bj = 0; bj < 4; bj++) {
        int row = wn * 64 + (bj * 2 + b_nbl) * 8 + (lid & 7);
        b_rel[bj] = A_BYTES + (uint32_t)row * 128u;
        b_sw[bj] = (uint32_t)(row & 7);
    }

    // ---- prologue: fill 3 of 4 stages ----
    load_stage(0, 0);
    load_stage(1, 1);
    load_stage(2, 2);

    for (int kt = 0; kt < NKT; kt++) {
        const int s = kt & 3;
        if (kt < NKT - 2) CP_WAIT(2);
        else if (kt == NKT - 2) CP_WAIT(1);
        else CP_WAIT(0);
        __syncthreads();

        if (kt + 3 < NKT) load_stage((kt + 3) & 3, kt + 3);

        // segment switch: fold f16 correction into the f32 accumulators
        if (kt == NSEG_KT) {
#pragma unroll
            for (int mi = 0; mi < 4; mi++)
#pragma unroll
                for (int ni = 0; ni < 8; ni++) {
                    float2 lo = __half22float2(*(__half2*)&acc_h[mi][ni][0]);
                    float2 hi = __half22float2(*(__half2*)&acc_h[mi][ni][1]);
                    acc_f[mi][ni][0] = lo.x; acc_f[mi][ni][1] = lo.y;
                    acc_f[mi][ni][2] = hi.x; acc_f[mi][ni][3] = hi.y;
                }
        }

        const uint32_t stb = sb + (uint32_t)s * STAGE_BYTES;
        if (kt < NSEG_KT) {
#pragma unroll
            for (int k16 = 0; k16 < 4; k16++) {
                uint32_t afr[4][4];
#pragma unroll
                for (int mi = 0; mi < 4; mi++) {
                    uint32_t c = (uint32_t)(k16 * 2 + a_half) ^ a_sw[mi];
                    ldsm_x4(afr[mi], stb + a_rel[mi] + c * 16u);
                }
                uint32_t bfr[8][2];
#pragma unroll
                for (int bj = 0; bj < 4; bj++) {
                    uint32_t c = (uint32_t)(k16 * 2 + b_kh) ^ b_sw[bj];
                    uint32_t r[4];
                    ldsm_x4(r, stb + b_rel[bj] + c * 16u);
                    bfr[bj * 2 + 0][0] = r[0]; bfr[bj * 2 + 0][1] = r[1];
                    bfr[bj * 2 + 1][0] = r[2]; bfr[bj * 2 + 1][1] = r[3];
                }
#pragma unroll
                for (int mi = 0; mi < 4; mi++)
#pragma unroll
                    for (int ni = 0; ni < 8; ni++)
                        mma_f16acc(acc_h[mi][ni], afr[mi], bfr[ni][0], bfr[ni][1]);
            }
        } else {
#pragma unroll
            for (int k16 = 0; k16 < 4; k16++) {
                uint32_t afr[4][4];
#pragma unroll
                for (int mi = 0; mi < 4; mi++) {
                    uint32_t c = (uint32_t)(k16 * 2 + a_half) ^ a_sw[mi];
                    ldsm_x4(afr[mi], stb + a_rel[mi] + c * 16u);
                }
                uint32_t bfr[8][2];
#pragma unroll
                for (int bj = 0; bj < 4; bj++) {
                    uint32_t c = (uint32_t)(k16 * 2 + b_kh) ^ b_sw[bj];
                    uint32_t r[4];
                    ldsm_x4(r, stb + b_rel[bj] + c * 16u);
                    bfr[bj * 2 + 0][0] = r[0]; bfr[bj * 2 + 0][1] = r[1];
                    bfr[bj * 2 + 1][0] = r[2]; bfr[bj * 2 + 1][1] = r[3];
                }
#pragma unroll
                for (int mi = 0; mi < 4; mi++)
#pragma unroll
                    for (int ni = 0; ni < 8; ni++)
                        mma_f32acc(acc_f[mi][ni], afr[mi], bfr[ni][0], bfr[ni][1]);
            }
        }
    }

    // ---- epilogue: bias + store ----
#pragma unroll
    for (int ni = 0; ni < 8; ni++) {
        const int gc = bn + wn * 64 + ni * 8 + (lid & 3) * 2;
        const float2 bv = *(const float2*)&bias[gc];
#pragma unroll
        for (int mi = 0; mi < 4; mi++) {
            const int gr = bm + wm * 64 + mi * 16 + (lid >> 2);
            float2 o0, o1;
            o0.x = acc_f[mi][ni][0] + bv.x;
            o0.y = acc_f[mi][ni][1] + bv.y;
            o1.x = acc_f[mi][ni][2] + bv.x;
            o1.y = acc_f[mi][ni][3] + bv.y;
            *(float2*)&C[(size_t)gr * N_DIM + gc] = o0;
            *(float2*)&C[(size_t)(gr + 8) * N_DIM + gc] = o1;
        }
    }
}

// ---------------------------------------------------------------------------
extern "C" void kernel_launch(void* const* d_in, const int* in_sizes, int n_in,
                              void* d_out, int out_size) {
    const float* x  = (const float*)d_in[0];   // [4,2048,4096]
    const float* w  = (const float*)d_in[1];   // [4096,4096] (out,in)
    const float* b  = (const float*)d_in[2];   // [4096]
    const float* la = (const float*)d_in[3];   // [4096,16]
    const float* lb = (const float*)d_in[4];   // [16,4096]
    float* out = (float*)d_out;

    prep_kernel<<<dim3(16384, 2), 256>>>(x, w, la, lb);

    cudaFuncSetAttribute(gemm_hmma_kernel,
                         cudaFuncAttributeMaxDynamicSharedMemorySize, SMEM_DYN);
    gemm_hmma_kernel<<<dim3(N_DIM / BN, M_DIM / BM), NTHREADS, SMEM_DYN>>>(b, out);
}